// round 5
// baseline (speedup 1.0000x reference)
#include <cuda_runtime.h>
#include <cuda_bf16.h>
#include <cstdint>

// Problem constants (shape-fixed per reference)
#define NMAX 50048
#define EMAX 400000

// Scratch (device globals: allocation-free rule)
__device__ float g_msgs[(size_t)EMAX * 128];
__device__ float g_gate[EMAX];
__device__ float g_wexp[EMAX];
__device__ int   g_segmax[NMAX];
__device__ float g_denom[NMAX];
__device__ float g_aggr[(size_t)NMAX * 128];

// ---------- float ordered-int encoding for atomicMax on floats ----------
__device__ __forceinline__ int f2ord(float f) {
    int i = __float_as_int(f);
    return (i >= 0) ? i : (i ^ 0x7fffffff);
}
__device__ __forceinline__ float ord2f(int o) {
    return __int_as_float((o >= 0) ? o : (o ^ 0x7fffffff));
}

// ---------- tf32 helpers ----------
__device__ __forceinline__ uint32_t f2tf32(float f) {
    uint32_t r;
    asm("cvt.rna.tf32.f32 %0, %1;" : "=r"(r) : "f"(f));
    return r;
}

__device__ __forceinline__ void mma_tf32(float c[4],
    uint32_t a0, uint32_t a1, uint32_t a2, uint32_t a3,
    uint32_t b0, uint32_t b1)
{
    asm volatile(
        "mma.sync.aligned.m16n8k8.row.col.f32.tf32.tf32.f32 "
        "{%0,%1,%2,%3}, {%4,%5,%6,%7}, {%8,%9}, {%0,%1,%2,%3};"
        : "+f"(c[0]), "+f"(c[1]), "+f"(c[2]), "+f"(c[3])
        : "r"(a0), "r"(a1), "r"(a2), "r"(a3), "r"(b0), "r"(b1));
}

__device__ __forceinline__ uint32_t smem_u32(const void* p) {
    return (uint32_t)__cvta_generic_to_shared(p);
}

// Weight double-buffer stride (words): 16 rows x max LDW (256+4)
#define SW_BUF 4160

// ---------------------------------------------------------------------------
// Tensor-core MLP layer over a 64-row tile, cp.async-pipelined weights.
//   sOut[64][NOUT] = act(sIn[64][K] @ W[K][NOUT] + B)
// 256 threads = 8 warps tiled 2(M: 32 rows) x 4(N: NOUT/4 cols).
// sIn/sOut hold fp32; cvt to tf32 happens at fragment load.
// Weights stream via cp.async into sW[2][16][LDW], double-buffered:
// slab s+1 is in flight while slab s computes.
// LDIN/LDOUT % 32 == 20 or 4; LDW = NOUT+4 (% 32 == 4): conflict-free LDS.
// ---------------------------------------------------------------------------
template<int K, int NOUT, bool RELU, int LDIN, int LDOUT>
__device__ __forceinline__ void mma_layer(
    const float* __restrict__ sIn,
    const float* __restrict__ W, const float* __restrict__ Bv,
    float* __restrict__ sOut, float* __restrict__ sW,
    float* __restrict__ gOut, int row0_global, int row_limit)
{
    constexpr int NT    = NOUT / 32;   // n8-tiles per warp
    constexpr int LDW   = NOUT + 4;
    constexpr int NSLAB = K / 16;      // K is a multiple of 16 everywhere
    constexpr int CH    = 16 * NOUT / 4;   // 16B chunks per slab
    constexpr int CPR   = NOUT / 4;        // chunks per row (power of two)

    const int tid   = threadIdx.x;
    const int lane  = tid & 31;
    const int warp  = tid >> 5;
    const int mwarp = warp & 1;
    const int nwarp = warp >> 1;
    const int g     = lane >> 2;
    const int tg    = lane & 3;
    const int n_base = nwarp * (NOUT / 4);

    // issue cp.async for weight slab s into buffer buf
    auto issue = [&](int s, int buf) {
        const float* src0 = W + (size_t)s * 16 * NOUT;
        float* dst0 = sW + buf * SW_BUF;
#pragma unroll
        for (int c = tid; c < CH; c += 256) {
            int row = c / CPR;
            int off = (c - row * CPR) * 4;
            uint32_t daddr = smem_u32(dst0 + row * LDW + off);
            asm volatile("cp.async.ca.shared.global [%0], [%1], 16;"
                         :: "r"(daddr), "l"(src0 + row * NOUT + off));
        }
        asm volatile("cp.async.commit_group;");
    };

    float acc[2][NT][4];
#pragma unroll
    for (int mt = 0; mt < 2; mt++)
#pragma unroll
        for (int nt = 0; nt < NT; nt++)
#pragma unroll
            for (int q = 0; q < 4; q++) acc[mt][nt][q] = 0.f;

    // prologue: 2 slabs in flight
    issue(0, 0);
    if (NSLAB > 1) issue(1, 1);

    for (int s = 0; s < NSLAB; s++) {
        if (s + 1 < NSLAB)
            asm volatile("cp.async.wait_group 1;" ::: "memory");
        else
            asm volatile("cp.async.wait_group 0;" ::: "memory");
        __syncthreads();   // weights for slab s visible to all; also orders sIn

        const float* buf = sW + (s & 1) * SW_BUF;
        const int kc = s * 16;
#pragma unroll
        for (int kk = 0; kk < 16; kk += 8) {
            uint32_t a[2][4];
#pragma unroll
            for (int mt = 0; mt < 2; mt++) {
                int r0 = mwarp * 32 + mt * 16 + g;
                const float* p = sIn + r0 * LDIN + kc + kk + tg;
                a[mt][0] = f2tf32(p[0]);
                a[mt][2] = f2tf32(p[4]);
                const float* q = p + 8 * LDIN;
                a[mt][1] = f2tf32(q[0]);
                a[mt][3] = f2tf32(q[4]);
            }
            uint32_t b[NT][2];
#pragma unroll
            for (int nt = 0; nt < NT; nt++) {
                int c = n_base + nt * 8 + g;
                b[nt][0] = f2tf32(buf[(kk + tg) * LDW + c]);
                b[nt][1] = f2tf32(buf[(kk + tg + 4) * LDW + c]);
            }
#pragma unroll
            for (int mt = 0; mt < 2; mt++)
#pragma unroll
                for (int nt = 0; nt < NT; nt++)
                    mma_tf32(acc[mt][nt],
                             a[mt][0], a[mt][1], a[mt][2], a[mt][3],
                             b[nt][0], b[nt][1]);
        }

        if (s + 2 < NSLAB) {
            __syncthreads();          // all reads of buf (s&1) done
            issue(s + 2, s & 1);      // refill it
        }
    }

    // ---- epilogue: bias (+relu), fp32 to sOut (and gOut) ----
#pragma unroll
    for (int nt = 0; nt < NT; nt++) {
        int c = n_base + nt * 8 + 2 * tg;
        float b0 = __ldg(Bv + c);
        float b1 = __ldg(Bv + c + 1);
#pragma unroll
        for (int mt = 0; mt < 2; mt++) {
#pragma unroll
            for (int h = 0; h < 2; h++) {
                int r = mwarp * 32 + mt * 16 + g + h * 8;
                float v0 = acc[mt][nt][h * 2 + 0] + b0;
                float v1 = acc[mt][nt][h * 2 + 1] + b1;
                if (RELU) { v0 = fmaxf(v0, 0.f); v1 = fmaxf(v1, 0.f); }
                *(float2*)(sOut + r * LDOUT + c) = make_float2(v0, v1);
                if (gOut != nullptr && row0_global + r < row_limit)
                    *(float2*)(gOut + (size_t)(row0_global + r) * NOUT + c) =
                        make_float2(v0, v1);
            }
        }
    }
    __syncthreads();   // sOut complete; sW free for next layer
}

// ---------------------------------------------------------------------------
// Kernel 1: init scratch
// ---------------------------------------------------------------------------
__global__ void init_kernel(int N) {
    int idx = blockIdx.x * blockDim.x + threadIdx.x;
    int total = N * 128;
    if (idx < total) g_aggr[idx] = 0.f;
    if (idx < N) {
        g_denom[idx] = 0.f;
        g_segmax[idx] = int(0x80000000);
    }
}

// ---------------------------------------------------------------------------
// Kernel 2: fused edge-MLP + gate-MLP. 64 edges / block.
// smem (floats): sA[64*276] | sB[64*260] | sW[2*SW_BUF]
// ---------------------------------------------------------------------------
__global__ __launch_bounds__(256, 1)
void edge_kernel(
    const float* __restrict__ nodes, const float* __restrict__ edges,
    const int* __restrict__ senders, const int* __restrict__ receivers,
    const float* __restrict__ w1, const float* __restrict__ b1,
    const float* __restrict__ w2, const float* __restrict__ b2,
    const float* __restrict__ w3, const float* __restrict__ b3,
    const float* __restrict__ aw1, const float* __restrict__ ab1,
    const float* __restrict__ aw2, const float* __restrict__ ab2,
    const float* __restrict__ aw3, const float* __restrict__ ab3,
    int E)
{
    extern __shared__ float smem[];
    float* sA = smem;                 // 64*276
    float* sB = sA + 64 * 276;        // 64*260
    float* sW = sB + 64 * 260;        // 2*SW_BUF

    const int tid  = threadIdx.x;
    const int lane = tid & 31;
    const int warp = tid >> 5;
    const int e0   = blockIdx.x * 64;

    // ---- gather feats = [edge(16) | nodes[s](128) | nodes[r](128)] (fp32) ----
#pragma unroll
    for (int i = 0; i < 8; i++) {
        int e = warp * 8 + i;
        int eg = e0 + e;
        int egc = eg < E ? eg : E - 1;
        int s = senders[egc];
        int r = receivers[egc];
        float* dst = sA + e * 276;
        if (lane < 4)
            *(float4*)(dst + lane * 4) = *(const float4*)(edges + (size_t)egc * 16 + lane * 4);
        *(float4*)(dst + 16 + lane * 4)  = *(const float4*)(nodes + (size_t)s * 128 + lane * 4);
        *(float4*)(dst + 144 + lane * 4) = *(const float4*)(nodes + (size_t)r * 128 + lane * 4);
    }
    // (first sync inside mma_layer orders the gather)

    // ---- message MLP ----
    mma_layer<272, 256, true , 276, 260>(sA, w1, b1, sB, sW, nullptr, 0, 0);
    mma_layer<256, 256, false, 260, 260>(sB, w2, b2, sA, sW, nullptr, 0, 0);
    mma_layer<256, 128, false, 260, 132>(sA, w3, b3, sB, sW, g_msgs, e0, E);

    // ---- gate MLP ----
    mma_layer<128, 128, true , 132, 132>(sB, aw1, ab1, sA, sW, nullptr, 0, 0);
    mma_layer<128, 128, false, 132, 132>(sA, aw2, ab2, sB, sW, nullptr, 0, 0);

    // gate = g2 @ aw3 + ab3  (128 -> 1), one warp per 8 edges
#pragma unroll
    for (int i = 0; i < 8; i++) {
        int e = warp * 8 + i;
        float p = 0.f;
#pragma unroll
        for (int j = 0; j < 4; j++)
            p += sB[e * 132 + lane + 32 * j] * __ldg(aw3 + lane + 32 * j);
#pragma unroll
        for (int off = 16; off > 0; off >>= 1)
            p += __shfl_xor_sync(0xffffffffu, p, off);
        if (lane == 0) {
            int eg = e0 + e;
            if (eg < E) {
                float gate = p + __ldg(ab3);
                g_gate[eg] = gate;
                int r = receivers[eg];
                atomicMax(&g_segmax[r], f2ord(gate));
            }
        }
    }
}

// ---------------------------------------------------------------------------
// Kernel 3: w = exp(gate - segmax[recv]); denom[recv] += w
// ---------------------------------------------------------------------------
__global__ void softmax_kernel(const int* __restrict__ receivers, int E) {
    int e = blockIdx.x * blockDim.x + threadIdx.x;
    if (e >= E) return;
    int r = receivers[e];
    float m = ord2f(g_segmax[r]);
    float w = expf(g_gate[e] - m);
    g_wexp[e] = w;
    atomicAdd(&g_denom[r], w);
}

// ---------------------------------------------------------------------------
// Kernel 4: aggr[recv] += (w/denom[recv]) * msgs[e]   (warp per edge)
// ---------------------------------------------------------------------------
__global__ __launch_bounds__(256)
void aggr_kernel(const int* __restrict__ receivers, int E) {
    int warp = (blockIdx.x * blockDim.x + threadIdx.x) >> 5;
    int lane = threadIdx.x & 31;
    if (warp >= E) return;
    int r = receivers[warp];
    float attn = g_wexp[warp] / g_denom[r];
    float4 v = *(const float4*)(g_msgs + (size_t)warp * 128 + lane * 4);
    float* dst = g_aggr + (size_t)r * 128 + lane * 4;
    atomicAdd(dst + 0, attn * v.x);
    atomicAdd(dst + 1, attn * v.y);
    atomicAdd(dst + 2, attn * v.z);
    atomicAdd(dst + 3, attn * v.w);
}

// ---------------------------------------------------------------------------
// Kernel 5: node update MLP. 64 nodes / block.
// smem (floats): sA[64*260] | sB[64*260] | sW[2*SW_BUF]
// ---------------------------------------------------------------------------
__global__ __launch_bounds__(256, 1)
void node_kernel(
    const float* __restrict__ nodes,
    const float* __restrict__ uw1, const float* __restrict__ ub1,
    const float* __restrict__ uw2, const float* __restrict__ ub2,
    const float* __restrict__ uw3, const float* __restrict__ ub3,
    float* __restrict__ out, int N)
{
    extern __shared__ float smem[];
    float* sA = smem;                 // 64*260
    float* sB = sA + 64 * 260;        // 64*260
    float* sW = sB + 64 * 260;        // 2*SW_BUF

    const int tid  = threadIdx.x;
    const int lane = tid & 31;
    const int warp = tid >> 5;
    const int n0   = blockIdx.x * 64;

    // gather u = [node(128) | aggr(128)] (fp32)
#pragma unroll
    for (int i = 0; i < 8; i++) {
        int e = warp * 8 + i;
        int n = n0 + e;
        float* dst = sA + e * 260;
        if (n < N) {
            *(float4*)(dst + lane * 4)       = *(const float4*)(nodes + (size_t)n * 128 + lane * 4);
            *(float4*)(dst + 128 + lane * 4) = *(const float4*)(g_aggr + (size_t)n * 128 + lane * 4);
        } else {
            float4 z = make_float4(0.f, 0.f, 0.f, 0.f);
            *(float4*)(dst + lane * 4) = z;
            *(float4*)(dst + 128 + lane * 4) = z;
        }
    }

    mma_layer<256, 256, true , 260, 260>(sA, uw1, ub1, sB, sW, nullptr, 0, 0);
    mma_layer<256, 256, false, 260, 260>(sB, uw2, ub2, sA, sW, nullptr, 0, 0);
    mma_layer<256, 128, false, 260, 132>(sA, uw3, ub3, sB, sW, out, n0, N);
}

// ---------------------------------------------------------------------------
extern "C" void kernel_launch(void* const* d_in, const int* in_sizes, int n_in,
                              void* d_out, int out_size)
{
    const float* nodes     = (const float*)d_in[0];
    const float* edges     = (const float*)d_in[1];
    const int*   senders   = (const int*)  d_in[2];
    const int*   receivers = (const int*)  d_in[3];
    const float* mw1 = (const float*)d_in[4];  const float* mb1 = (const float*)d_in[5];
    const float* mw2 = (const float*)d_in[6];  const float* mb2 = (const float*)d_in[7];
    const float* mw3 = (const float*)d_in[8];  const float* mb3 = (const float*)d_in[9];
    const float* aw1 = (const float*)d_in[10]; const float* ab1 = (const float*)d_in[11];
    const float* aw2 = (const float*)d_in[12]; const float* ab2 = (const float*)d_in[13];
    const float* aw3 = (const float*)d_in[14]; const float* ab3 = (const float*)d_in[15];
    const float* uw1 = (const float*)d_in[16]; const float* ub1 = (const float*)d_in[17];
    const float* uw2 = (const float*)d_in[18]; const float* ub2 = (const float*)d_in[19];
    const float* uw3 = (const float*)d_in[20]; const float* ub3 = (const float*)d_in[21];
    float* out = (float*)d_out;

    const int N = in_sizes[0] / 128;
    const int E = in_sizes[2];

    const int EDGE_SMEM = (64 * 276 + 64 * 260 + 2 * SW_BUF) * 4;  // 170496 B
    const int NODE_SMEM = (64 * 260 + 64 * 260 + 2 * SW_BUF) * 4;  // 166400 B
    cudaFuncSetAttribute(edge_kernel, cudaFuncAttributeMaxDynamicSharedMemorySize, EDGE_SMEM);
    cudaFuncSetAttribute(node_kernel, cudaFuncAttributeMaxDynamicSharedMemorySize, NODE_SMEM);

    // 1) init scratch
    {
        int total = N * 128;
        init_kernel<<<(total + 255) / 256, 256>>>(N);
    }
    // 2) edge + gate MLP (tensor cores, cp.async pipelined)
    {
        int blocks = (E + 63) / 64;
        edge_kernel<<<blocks, 256, EDGE_SMEM>>>(
            nodes, edges, senders, receivers,
            mw1, mb1, mw2, mb2, mw3, mb3,
            aw1, ab1, aw2, ab2, aw3, ab3, E);
    }
    // 3) softmax numerator + denom
    softmax_kernel<<<(E + 255) / 256, 256>>>(receivers, E);
    // 4) attention-weighted scatter
    {
        int blocks = (E + 7) / 8;
        aggr_kernel<<<blocks, 256>>>(receivers, E);
    }
    // 5) node update (tensor cores, cp.async pipelined)
    {
        int blocks = (N + 63) / 64;
        node_kernel<<<blocks, 256, NODE_SMEM>>>(
            nodes, uw1, ub1, uw2, ub2, uw3, ub3, out, N);
    }
}

// round 6
// speedup vs baseline: 2.2166x; 2.2166x over previous
#include <cuda_runtime.h>
#include <cuda_fp16.h>
#include <cstdint>

#define NMAX 50048
#define EMAX 400000

__device__ float g_msgs[(size_t)EMAX * 128];
__device__ float g_gate[EMAX];
__device__ float g_wexp[EMAX];
__device__ int   g_segmax[NMAX];
__device__ float g_denom[NMAX];
__device__ float g_aggr[(size_t)NMAX * 128];
// packed fp16 weights: per 16-K slab, [NOUT][24] halves (48B rows, k in cols 0..15)
__device__ __align__(16) unsigned char g_wpack[1093632];

// byte offsets of each packed matrix (slabs*NOUT*48)
#define OFF_MW1 0u
#define OFF_MW2 208896u
#define OFF_MW3 405504u
#define OFF_AW1 503808u
#define OFF_AW2 552960u
#define OFF_UW1 602112u
#define OFF_UW2 798720u
#define OFF_UW3 995328u

__device__ __forceinline__ int f2ord(float f) {
    int i = __float_as_int(f);
    return (i >= 0) ? i : (i ^ 0x7fffffff);
}
__device__ __forceinline__ float ord2f(int o) {
    return __int_as_float((o >= 0) ? o : (o ^ 0x7fffffff));
}
__device__ __forceinline__ uint32_t smem_u32(const void* p) {
    return (uint32_t)__cvta_generic_to_shared(p);
}
__device__ __forceinline__ void ldsm4(uint32_t& r0, uint32_t& r1,
                                      uint32_t& r2, uint32_t& r3, uint32_t a) {
    asm volatile("ldmatrix.sync.aligned.m8n8.x4.shared.b16 {%0,%1,%2,%3}, [%4];"
                 : "=r"(r0), "=r"(r1), "=r"(r2), "=r"(r3) : "r"(a));
}
__device__ __forceinline__ void mma_f16(float c[4],
    uint32_t a0, uint32_t a1, uint32_t a2, uint32_t a3, uint32_t b0, uint32_t b1)
{
    asm volatile(
        "mma.sync.aligned.m16n8k16.row.col.f32.f16.f16.f32 "
        "{%0,%1,%2,%3}, {%4,%5,%6,%7}, {%8,%9}, {%0,%1,%2,%3};"
        : "+f"(c[0]), "+f"(c[1]), "+f"(c[2]), "+f"(c[3])
        : "r"(a0), "r"(a1), "r"(a2), "r"(a3), "r"(b0), "r"(b1));
}

#define SWBUF_BYTES 12288   // one slab buffer (max NOUT=256: 256*48)

// ---------------------------------------------------------------------------
// fp16 tensor-core MLP layer over a 64-row tile.
// sOut[64][NOUT] = act(sIn[64][K] @ W + B);  W pre-packed n-major fp16 slabs.
// 8 warps = 2(M:32 rows) x 4(N: NOUT/4 cols). A/B frags via ldmatrix.x4.
// cp.async double-buffers weight slabs (flat byte copy, layout matches smem).
// ---------------------------------------------------------------------------
template<int K, int NOUT, bool RELU, int LDIN, int LDOUT>
__device__ __forceinline__ void mma_layer(
    const __half* __restrict__ sIn, const unsigned char* __restrict__ Wp,
    const float* __restrict__ Bv, __half* __restrict__ sOut,
    unsigned char* __restrict__ sW,
    float* __restrict__ gOut, int row0_global, int row_limit)
{
    constexpr int NT = NOUT / 32;          // n8 tiles per warp
    constexpr int NSLAB = K / 16;
    constexpr int SLAB = NOUT * 48;
    constexpr int CH = SLAB / 16;
    const int tid = threadIdx.x, lane = tid & 31, warp = tid >> 5;
    const int mwarp = warp & 1, nwarp = warp >> 1;
    const int n_base = nwarp * (NOUT / 4);
    const int g = lane >> 2, tg = lane & 3;
    // ldmatrix lane->offset maps
    const int a_row = (lane & 7) + ((lane >> 3) & 1) * 8;
    const int a_k   = (lane >> 4) * 8;
    const int b_n   = ((lane >> 4) & 1) * 8 + (lane & 7);
    const int b_k   = ((lane >> 3) & 1) * 8;

    auto issue = [&](int s, int buf) {
        const unsigned char* src = Wp + (size_t)s * SLAB;
        unsigned char* dst = sW + buf * SWBUF_BYTES;
        for (int c = tid; c < CH; c += 256) {
            uint32_t daddr = smem_u32(dst + c * 16);
            asm volatile("cp.async.ca.shared.global [%0], [%1], 16;"
                         :: "r"(daddr), "l"(src + c * 16));
        }
        asm volatile("cp.async.commit_group;");
    };

    float acc[2][NT][4];
#pragma unroll
    for (int mt = 0; mt < 2; mt++)
#pragma unroll
        for (int nt = 0; nt < NT; nt++)
#pragma unroll
            for (int q = 0; q < 4; q++) acc[mt][nt][q] = 0.f;

    issue(0, 0);
    if (NSLAB > 1) issue(1, 1);

    for (int s = 0; s < NSLAB; s++) {
        if (s + 1 < NSLAB)
            asm volatile("cp.async.wait_group 1;" ::: "memory");
        else
            asm volatile("cp.async.wait_group 0;" ::: "memory");
        __syncthreads();

        const unsigned char* buf = sW + (s & 1) * SWBUF_BYTES;
        const int kc = s * 16;
        uint32_t A[2][4];
#pragma unroll
        for (int mt = 0; mt < 2; mt++) {
            uint32_t ap = smem_u32(
                sIn + (mwarp * 32 + mt * 16 + a_row) * LDIN + kc + a_k);
            ldsm4(A[mt][0], A[mt][1], A[mt][2], A[mt][3], ap);
        }
#pragma unroll
        for (int ng = 0; ng < NT / 2; ng++) {
            int n0 = n_base + ng * 16;
            uint32_t bp = smem_u32(buf + (n0 + b_n) * 48 + b_k * 2);
            uint32_t B0, B1, B2, B3;
            ldsm4(B0, B1, B2, B3, bp);
            mma_f16(acc[0][2 * ng], A[0][0], A[0][1], A[0][2], A[0][3], B0, B1);
            mma_f16(acc[1][2 * ng], A[1][0], A[1][1], A[1][2], A[1][3], B0, B1);
            mma_f16(acc[0][2 * ng + 1], A[0][0], A[0][1], A[0][2], A[0][3], B2, B3);
            mma_f16(acc[1][2 * ng + 1], A[1][0], A[1][1], A[1][2], A[1][3], B2, B3);
        }
        if (s + 2 < NSLAB) {
            __syncthreads();
            issue(s + 2, s & 1);
        }
    }

    // epilogue: bias (+relu), fp16 to sOut, optional fp32 to gOut
#pragma unroll
    for (int nt = 0; nt < NT; nt++) {
        int c = n_base + nt * 8 + 2 * tg;
        float b0 = __ldg(Bv + c), b1 = __ldg(Bv + c + 1);
#pragma unroll
        for (int mt = 0; mt < 2; mt++) {
#pragma unroll
            for (int h = 0; h < 2; h++) {
                int r = mwarp * 32 + mt * 16 + g + h * 8;
                float v0 = acc[mt][nt][h * 2 + 0] + b0;
                float v1 = acc[mt][nt][h * 2 + 1] + b1;
                if (RELU) { v0 = fmaxf(v0, 0.f); v1 = fmaxf(v1, 0.f); }
                *(__half2*)(sOut + r * LDOUT + c) = __floats2half2_rn(v0, v1);
                if (gOut != nullptr && row0_global + r < row_limit)
                    *(float2*)(gOut + (size_t)(row0_global + r) * NOUT + c) =
                        make_float2(v0, v1);
            }
        }
    }
    __syncthreads();
}

// ---------------------------------------------------------------------------
__global__ void pack_kernel(const float* __restrict__ src, int K, int N,
                            unsigned int dstoff) {
    int idx = blockIdx.x * blockDim.x + threadIdx.x;
    if (idx >= K * N) return;
    int k = idx / N, n = idx - k * N;
    __half* dst = (__half*)(g_wpack + dstoff);
    dst[((size_t)(k >> 4) * N + n) * 24 + (k & 15)] = __float2half_rn(src[idx]);
}

__global__ void init_kernel(int N) {
    int idx = blockIdx.x * blockDim.x + threadIdx.x;
    if (idx < N * 128) g_aggr[idx] = 0.f;
    if (idx < N) { g_denom[idx] = 0.f; g_segmax[idx] = int(0x80000000); }
}

// ---------------------------------------------------------------------------
// edge kernel: smem bytes: sA[64*280 h]=35840 | sB[64*264 h]=33792 | sW 24576
// ---------------------------------------------------------------------------
__global__ __launch_bounds__(256, 2)
void edge_kernel(
    const float* __restrict__ nodes, const float* __restrict__ edges,
    const int* __restrict__ senders, const int* __restrict__ receivers,
    const float* __restrict__ b1, const float* __restrict__ b2,
    const float* __restrict__ b3, const float* __restrict__ ab1,
    const float* __restrict__ ab2,
    const float* __restrict__ aw3, const float* __restrict__ ab3, int E)
{
    extern __shared__ unsigned char smem[];
    __half* sA = (__half*)smem;                    // stride 280
    __half* sB = (__half*)(smem + 35840);          // stride 264 (or 136)
    unsigned char* sW = smem + 69632;

    const int tid = threadIdx.x, lane = tid & 31, warp = tid >> 5;
    const int e0 = blockIdx.x * 64;

#pragma unroll
    for (int i = 0; i < 8; i++) {
        int e = warp * 8 + i;
        int eg = e0 + e;
        int egc = eg < E ? eg : E - 1;
        int s = senders[egc], r = receivers[egc];
        __half* dst = sA + e * 280;
        if (lane < 4) {
            float4 v = *(const float4*)(edges + (size_t)egc * 16 + lane * 4);
            *(__half2*)(dst + lane * 4)     = __floats2half2_rn(v.x, v.y);
            *(__half2*)(dst + lane * 4 + 2) = __floats2half2_rn(v.z, v.w);
        }
        float4 vs = *(const float4*)(nodes + (size_t)s * 128 + lane * 4);
        *(__half2*)(dst + 16 + lane * 4)     = __floats2half2_rn(vs.x, vs.y);
        *(__half2*)(dst + 16 + lane * 4 + 2) = __floats2half2_rn(vs.z, vs.w);
        float4 vr = *(const float4*)(nodes + (size_t)r * 128 + lane * 4);
        *(__half2*)(dst + 144 + lane * 4)     = __floats2half2_rn(vr.x, vr.y);
        *(__half2*)(dst + 144 + lane * 4 + 2) = __floats2half2_rn(vr.z, vr.w);
    }

    mma_layer<272, 256, true , 280, 264>(sA, g_wpack + OFF_MW1, b1, sB, sW, nullptr, 0, 0);
    mma_layer<256, 256, false, 264, 280>(sB, g_wpack + OFF_MW2, b2, sA, sW, nullptr, 0, 0);
    mma_layer<256, 128, false, 280, 136>(sA, g_wpack + OFF_MW3, b3, sB, sW, g_msgs, e0, E);
    mma_layer<128, 128, true , 136, 136>(sB, g_wpack + OFF_AW1, ab1, sA, sW, nullptr, 0, 0);
    mma_layer<128, 128, false, 136, 136>(sA, g_wpack + OFF_AW2, ab2, sB, sW, nullptr, 0, 0);

    // gate = g2 @ aw3 + ab3 (128 -> 1), one warp per 8 edges
#pragma unroll
    for (int i = 0; i < 8; i++) {
        int e = warp * 8 + i;
        float p = 0.f;
#pragma unroll
        for (int j = 0; j < 4; j++)
            p += __half2float(sB[e * 136 + lane + 32 * j]) * __ldg(aw3 + lane + 32 * j);
#pragma unroll
        for (int off = 16; off > 0; off >>= 1)
            p += __shfl_xor_sync(0xffffffffu, p, off);
        if (lane == 0) {
            int eg = e0 + e;
            if (eg < E) {
                float gate = p + __ldg(ab3);
                g_gate[eg] = gate;
                atomicMax(&g_segmax[receivers[eg]], f2ord(gate));
            }
        }
    }
}

__global__ void softmax_kernel(const int* __restrict__ receivers, int E) {
    int e = blockIdx.x * blockDim.x + threadIdx.x;
    if (e >= E) return;
    int r = receivers[e];
    float w = expf(g_gate[e] - ord2f(g_segmax[r]));
    g_wexp[e] = w;
    atomicAdd(&g_denom[r], w);
}

__global__ __launch_bounds__(256)
void aggr_kernel(const int* __restrict__ receivers, int E) {
    int warp = (blockIdx.x * blockDim.x + threadIdx.x) >> 5;
    int lane = threadIdx.x & 31;
    if (warp >= E) return;
    int r = receivers[warp];
    float attn = g_wexp[warp] / g_denom[r];
    float4 v = *(const float4*)(g_msgs + (size_t)warp * 128 + lane * 4);
    float* dst = g_aggr + (size_t)r * 128 + lane * 4;
    atomicAdd(dst + 0, attn * v.x);
    atomicAdd(dst + 1, attn * v.y);
    atomicAdd(dst + 2, attn * v.z);
    atomicAdd(dst + 3, attn * v.w);
}

// ---------------------------------------------------------------------------
// node kernel: smem: sA[64*264 h]=33792 | sB 33792 | sW 24576
// ---------------------------------------------------------------------------
__global__ __launch_bounds__(256, 2)
void node_kernel(
    const float* __restrict__ nodes,
    const float* __restrict__ ub1, const float* __restrict__ ub2,
    const float* __restrict__ ub3, float* __restrict__ out, int N)
{
    extern __shared__ unsigned char smem[];
    __half* sA = (__half*)smem;                    // stride 264
    __half* sB = (__half*)(smem + 33792);
    unsigned char* sW = smem + 67584;

    const int tid = threadIdx.x, lane = tid & 31, warp = tid >> 5;
    const int n0 = blockIdx.x * 64;

#pragma unroll
    for (int i = 0; i < 8; i++) {
        int e = warp * 8 + i;
        int n = n0 + e;
        __half* dst = sA + e * 264;
        if (n < N) {
            float4 v0 = *(const float4*)(nodes + (size_t)n * 128 + lane * 4);
            *(__half2*)(dst + lane * 4)     = __floats2half2_rn(v0.x, v0.y);
            *(__half2*)(dst + lane * 4 + 2) = __floats2half2_rn(v0.z, v0.w);
            float4 v1 = *(const float4*)(g_aggr + (size_t)n * 128 + lane * 4);
            *(__half2*)(dst + 128 + lane * 4)     = __floats2half2_rn(v1.x, v1.y);
            *(__half2*)(dst + 128 + lane * 4 + 2) = __floats2half2_rn(v1.z, v1.w);
        } else {
            *(float2*)(dst + lane * 4) = make_float2(0.f, 0.f);
            *(float2*)(dst + 128 + lane * 4) = make_float2(0.f, 0.f);
        }
    }

    mma_layer<256, 256, true , 264, 264>(sA, g_wpack + OFF_UW1, ub1, sB, sW, nullptr, 0, 0);
    mma_layer<256, 256, false, 264, 264>(sB, g_wpack + OFF_UW2, ub2, sA, sW, nullptr, 0, 0);
    mma_layer<256, 128, false, 264, 136>(sA, g_wpack + OFF_UW3, ub3, sB, sW, out, n0, N);
}

// ---------------------------------------------------------------------------
extern "C" void kernel_launch(void* const* d_in, const int* in_sizes, int n_in,
                              void* d_out, int out_size)
{
    const float* nodes     = (const float*)d_in[0];
    const float* edges     = (const float*)d_in[1];
    const int*   senders   = (const int*)  d_in[2];
    const int*   receivers = (const int*)  d_in[3];
    const float* mw1 = (const float*)d_in[4];  const float* mb1 = (const float*)d_in[5];
    const float* mw2 = (const float*)d_in[6];  const float* mb2 = (const float*)d_in[7];
    const float* mw3 = (const float*)d_in[8];  const float* mb3 = (const float*)d_in[9];
    const float* aw1 = (const float*)d_in[10]; const float* ab1 = (const float*)d_in[11];
    const float* aw2 = (const float*)d_in[12]; const float* ab2 = (const float*)d_in[13];
    const float* aw3 = (const float*)d_in[14]; const float* ab3 = (const float*)d_in[15];
    const float* uw1 = (const float*)d_in[16]; const float* ub1 = (const float*)d_in[17];
    const float* uw2 = (const float*)d_in[18]; const float* ub2 = (const float*)d_in[19];
    const float* uw3 = (const float*)d_in[20]; const float* ub3 = (const float*)d_in[21];
    float* out = (float*)d_out;

    const int N = in_sizes[0] / 128;
    const int E = in_sizes[2];

    const int EDGE_SMEM = 94208;
    const int NODE_SMEM = 92160;
    cudaFuncSetAttribute(edge_kernel, cudaFuncAttributeMaxDynamicSharedMemorySize, EDGE_SMEM);
    cudaFuncSetAttribute(node_kernel, cudaFuncAttributeMaxDynamicSharedMemorySize, NODE_SMEM);

    // 0) pack weights to fp16 slabs
    auto pk = [&](const float* w, int K, int Nn, unsigned int off) {
        pack_kernel<<<(K * Nn + 255) / 256, 256>>>(w, K, Nn, off);
    };
    pk(mw1, 272, 256, OFF_MW1); pk(mw2, 256, 256, OFF_MW2);
    pk(mw3, 256, 128, OFF_MW3); pk(aw1, 128, 128, OFF_AW1);
    pk(aw2, 128, 128, OFF_AW2); pk(uw1, 256, 256, OFF_UW1);
    pk(uw2, 256, 256, OFF_UW2); pk(uw3, 256, 128, OFF_UW3);

    // 1) init scratch
    init_kernel<<<(N * 128 + 255) / 256, 256>>>(N);
    // 2) edge + gate MLP
    edge_kernel<<<(E + 63) / 64, 256, EDGE_SMEM>>>(
        nodes, edges, senders, receivers,
        mb1, mb2, mb3, ab1, ab2, aw3, ab3, E);
    // 3) softmax
    softmax_kernel<<<(E + 255) / 256, 256>>>(receivers, E);
    // 4) scatter
    aggr_kernel<<<(E + 7) / 8, 256>>>(receivers, E);
    // 5) node update
    node_kernel<<<(N + 63) / 64, 256, NODE_SMEM>>>(
        nodes, ub1, ub2, ub3, out, N);
}

// round 8
// speedup vs baseline: 2.5983x; 1.1722x over previous
#include <cuda_runtime.h>
#include <cuda_fp16.h>
#include <cstdint>

#define NMAX 50048
#define EMAX 400000

__device__ float g_msgs[(size_t)EMAX * 128];
__device__ float g_gate[EMAX];
__device__ int   g_segmax[NMAX];
__device__ float g_denom[NMAX];
__device__ float g_aggr[(size_t)NMAX * 128];
// packed fp16 weights: per 16-K slab, [NOUT][24] halves (48B rows, k in cols 0..15)
__device__ __align__(16) unsigned char g_wpack[1093632];

#define OFF_MW1 0u
#define OFF_MW2 208896u
#define OFF_MW3 405504u
#define OFF_AW1 503808u
#define OFF_AW2 552960u
#define OFF_UW1 602112u
#define OFF_UW2 798720u
#define OFF_UW3 995328u

__device__ __forceinline__ int f2ord(float f) {
    int i = __float_as_int(f);
    return (i >= 0) ? i : (i ^ 0x7fffffff);
}
__device__ __forceinline__ float ord2f(int o) {
    return __int_as_float((o >= 0) ? o : (o ^ 0x7fffffff));
}
__device__ __forceinline__ uint32_t smem_u32(const void* p) {
    return (uint32_t)__cvta_generic_to_shared(p);
}
__device__ __forceinline__ void ldsm4(uint32_t& r0, uint32_t& r1,
                                      uint32_t& r2, uint32_t& r3, uint32_t a) {
    asm volatile("ldmatrix.sync.aligned.m8n8.x4.shared.b16 {%0,%1,%2,%3}, [%4];"
                 : "=r"(r0), "=r"(r1), "=r"(r2), "=r"(r3) : "r"(a));
}
__device__ __forceinline__ void mma_f16(float c[4],
    uint32_t a0, uint32_t a1, uint32_t a2, uint32_t a3, uint32_t b0, uint32_t b1)
{
    asm volatile(
        "mma.sync.aligned.m16n8k16.row.col.f32.f16.f16.f32 "
        "{%0,%1,%2,%3}, {%4,%5,%6,%7}, {%8,%9}, {%0,%1,%2,%3};"
        : "+f"(c[0]), "+f"(c[1]), "+f"(c[2]), "+f"(c[3])
        : "r"(a0), "r"(a1), "r"(a2), "r"(a3), "r"(b0), "r"(b1));
}

// per-warp weight region: 3 stages x 1536 B (max NW=32 cols x 48 B)
#define WSTAGE 1536
#define WREGION 4608

// ---------------------------------------------------------------------------
// Warp-autonomous fp16 tensor-core MLP layer over a 64-row tile.
// sOut[64][NOUT] = act(sIn[64][K] @ W + B).
// Each warp owns cols [warp*NW, (warp+1)*NW), NW = NOUT/8, all 64 rows
// (4 m16 tiles x NT n8 tiles). Weights stream per-warp via cp.async into a
// private triple-buffered region: no block-wide barriers inside the K loop.
// Safety of buffer recycle: refill is issued AFTER the MMAs in program order;
// in-order issue means MMAs (whose operands depend on the ldmatrix results)
// have issued, hence the ldmatrix reads of this stage completed.
// ---------------------------------------------------------------------------
template<int K, int NOUT, bool RELU, int LDIN, int LDOUT>
__device__ __forceinline__ void mma_layer(
    const __half* __restrict__ sIn, const unsigned char* __restrict__ Wp,
    const float* __restrict__ Bv, __half* __restrict__ sOut,
    unsigned char* __restrict__ sWbase,
    float* __restrict__ gOut, int row0, int rowlim)
{
    constexpr int NSLAB = K / 16;
    constexpr int NW = NOUT / 8;       // cols per warp (32 or 16)
    constexpr int NT = NW / 8;         // n8 tiles per warp (4 or 2)
    constexpr int WCH = NW * 48 / 16;  // 16B chunks per slab per warp
    const int tid = threadIdx.x, lane = tid & 31, warp = tid >> 5;
    const int n0 = warp * NW;
    unsigned char* wb = sWbase + warp * WREGION;
    const int g = lane >> 2, tg = lane & 3;
    const int a_row = (lane & 7) + ((lane >> 3) & 1) * 8;
    const int a_k   = (lane >> 4) * 8;
    const int b_n   = ((lane >> 4) & 1) * 8 + (lane & 7);
    const int b_k   = ((lane >> 3) & 1) * 8;

    auto issue = [&](int s) {
        if (s < NSLAB) {
            const unsigned char* src = Wp + ((size_t)s * NOUT + n0) * 48;
            unsigned char* dst = wb + (s % 3) * WSTAGE;
#pragma unroll
            for (int c = lane; c < WCH; c += 32) {
                uint32_t da = smem_u32(dst + c * 16);
                asm volatile("cp.async.ca.shared.global [%0], [%1], 16;"
                             :: "r"(da), "l"(src + c * 16));
            }
        }
        asm volatile("cp.async.commit_group;");
    };

    // start weight streaming before the input barrier (independent data)
    issue(0); issue(1); issue(2);
    __syncthreads();   // sIn ready (gather or previous layer's epilogue)

    float acc[4][NT][4];
#pragma unroll
    for (int mt = 0; mt < 4; mt++)
#pragma unroll
        for (int nt = 0; nt < NT; nt++)
#pragma unroll
            for (int q = 0; q < 4; q++) acc[mt][nt][q] = 0.f;

    for (int s = 0; s < NSLAB; s++) {
        asm volatile("cp.async.wait_group 2;" ::: "memory");
        __syncwarp();
        const unsigned char* buf = wb + (s % 3) * WSTAGE;
        const int kc = s * 16;
        uint32_t A[4][4];
#pragma unroll
        for (int mt = 0; mt < 4; mt++)
            ldsm4(A[mt][0], A[mt][1], A[mt][2], A[mt][3],
                  smem_u32(sIn + (mt * 16 + a_row) * LDIN + kc + a_k));
#pragma unroll
        for (int ng = 0; ng < NT / 2; ng++) {
            uint32_t B0, B1, B2, B3;
            ldsm4(B0, B1, B2, B3, smem_u32(buf + (ng * 16 + b_n) * 48 + b_k * 2));
#pragma unroll
            for (int mt = 0; mt < 4; mt++) {
                mma_f16(acc[mt][2 * ng],     A[mt][0], A[mt][1], A[mt][2], A[mt][3], B0, B1);
                mma_f16(acc[mt][2 * ng + 1], A[mt][0], A[mt][1], A[mt][2], A[mt][3], B2, B3);
            }
        }
        issue(s + 3);   // after MMAs: this stage's ldmatrix reads are complete
    }

    // epilogue: bias (+relu), fp16 to sOut, optional fp32 to gOut
#pragma unroll
    for (int nt = 0; nt < NT; nt++) {
        int c = n0 + nt * 8 + 2 * tg;
        float b0 = __ldg(Bv + c), b1 = __ldg(Bv + c + 1);
#pragma unroll
        for (int mt = 0; mt < 4; mt++) {
#pragma unroll
            for (int h = 0; h < 2; h++) {
                int r = mt * 16 + g + h * 8;
                float v0 = acc[mt][nt][h * 2 + 0] + b0;
                float v1 = acc[mt][nt][h * 2 + 1] + b1;
                if (RELU) { v0 = fmaxf(v0, 0.f); v1 = fmaxf(v1, 0.f); }
                *(__half2*)(sOut + r * LDOUT + c) = __floats2half2_rn(v0, v1);
                if (gOut != nullptr && row0 + r < rowlim)
                    *(float2*)(gOut + (size_t)(row0 + r) * NOUT + c) =
                        make_float2(v0, v1);
            }
        }
    }
    __syncthreads();
}

// ---------------------------------------------------------------------------
// One fused pack kernel: converts all 8 weight matrices to 16-K-slab fp16
// layout. Segments in idx order: mw1,mw2,mw3,aw1,aw2,uw1,uw2,uw3.
// ---------------------------------------------------------------------------
__device__ __forceinline__ void pack_one(const float* src, int idx, int N,
                                         unsigned int off) {
    int k = idx / N, n = idx - k * N;
    *(__half*)(g_wpack + off + (((size_t)(k >> 4) * N + n) * 24 + (k & 15)) * 2) =
        __float2half_rn(src[idx]);
}
__global__ void pack_kernel(
    const float* __restrict__ mw1, const float* __restrict__ mw2,
    const float* __restrict__ mw3, const float* __restrict__ aw1,
    const float* __restrict__ aw2, const float* __restrict__ uw1,
    const float* __restrict__ uw2, const float* __restrict__ uw3)
{
    int idx = blockIdx.x * blockDim.x + threadIdx.x;
    if      (idx <  69632) pack_one(mw1, idx,          256, OFF_MW1);
    else if (idx < 135168) pack_one(mw2, idx -  69632, 256, OFF_MW2);
    else if (idx < 167936) pack_one(mw3, idx - 135168, 128, OFF_MW3);
    else if (idx < 184320) pack_one(aw1, idx - 167936, 128, OFF_AW1);
    else if (idx < 200704) pack_one(aw2, idx - 184320, 128, OFF_AW2);
    else if (idx < 266240) pack_one(uw1, idx - 200704, 256, OFF_UW1);
    else if (idx < 331776) pack_one(uw2, idx - 266240, 256, OFF_UW2);
    else if (idx < 364544) pack_one(uw3, idx - 331776, 128, OFF_UW3);
}

__global__ void init_kernel(int N) {
    int idx = blockIdx.x * blockDim.x + threadIdx.x;
    if (idx < N * 128) g_aggr[idx] = 0.f;
    if (idx < N) { g_denom[idx] = 0.f; g_segmax[idx] = int(0x80000000); }
}

// ---------------------------------------------------------------------------
// edge kernel: smem: sA[64*280 h]=35840 | sB[64*264 h]=33792 | sW 8*4608=36864
// ---------------------------------------------------------------------------
__global__ __launch_bounds__(256, 2)
void edge_kernel(
    const float* __restrict__ nodes, const float* __restrict__ edges,
    const int* __restrict__ senders, const int* __restrict__ receivers,
    const float* __restrict__ b1, const float* __restrict__ b2,
    const float* __restrict__ b3, const float* __restrict__ ab1,
    const float* __restrict__ ab2,
    const float* __restrict__ aw3, const float* __restrict__ ab3, int E)
{
    extern __shared__ unsigned char smem[];
    __half* sA = (__half*)smem;                    // stride 280
    __half* sB = (__half*)(smem + 35840);          // stride 264 (or 136)
    unsigned char* sW = smem + 69632;

    const int tid = threadIdx.x, lane = tid & 31, warp = tid >> 5;
    const int e0 = blockIdx.x * 64;

#pragma unroll
    for (int i = 0; i < 8; i++) {
        int e = warp * 8 + i;
        int eg = e0 + e;
        int egc = eg < E ? eg : E - 1;
        int s = senders[egc], r = receivers[egc];
        __half* dst = sA + e * 280;
        if (lane < 4) {
            float4 v = *(const float4*)(edges + (size_t)egc * 16 + lane * 4);
            *(__half2*)(dst + lane * 4)     = __floats2half2_rn(v.x, v.y);
            *(__half2*)(dst + lane * 4 + 2) = __floats2half2_rn(v.z, v.w);
        }
        float4 vs = *(const float4*)(nodes + (size_t)s * 128 + lane * 4);
        *(__half2*)(dst + 16 + lane * 4)     = __floats2half2_rn(vs.x, vs.y);
        *(__half2*)(dst + 16 + lane * 4 + 2) = __floats2half2_rn(vs.z, vs.w);
        float4 vr = *(const float4*)(nodes + (size_t)r * 128 + lane * 4);
        *(__half2*)(dst + 144 + lane * 4)     = __floats2half2_rn(vr.x, vr.y);
        *(__half2*)(dst + 144 + lane * 4 + 2) = __floats2half2_rn(vr.z, vr.w);
    }
    // (mma_layer's entry __syncthreads orders the gather)

    mma_layer<272, 256, true , 280, 264>(sA, g_wpack + OFF_MW1, b1, sB, sW, nullptr, 0, 0);
    mma_layer<256, 256, false, 264, 280>(sB, g_wpack + OFF_MW2, b2, sA, sW, nullptr, 0, 0);
    mma_layer<256, 128, false, 280, 136>(sA, g_wpack + OFF_MW3, b3, sB, sW, g_msgs, e0, E);
    mma_layer<128, 128, true , 136, 136>(sB, g_wpack + OFF_AW1, ab1, sA, sW, nullptr, 0, 0);
    mma_layer<128, 128, false, 136, 136>(sA, g_wpack + OFF_AW2, ab2, sB, sW, nullptr, 0, 0);

    // gate = g2 @ aw3 + ab3 (128 -> 1), one warp per 8 edges
#pragma unroll
    for (int i = 0; i < 8; i++) {
        int e = warp * 8 + i;
        float p = 0.f;
#pragma unroll
        for (int j = 0; j < 4; j++)
            p += __half2float(sB[e * 136 + lane + 32 * j]) * __ldg(aw3 + lane + 32 * j);
#pragma unroll
        for (int off = 16; off > 0; off >>= 1)
            p += __shfl_xor_sync(0xffffffffu, p, off);
        if (lane == 0) {
            int eg = e0 + e;
            if (eg < E) {
                float gate = p + __ldg(ab3);
                g_gate[eg] = gate;
                atomicMax(&g_segmax[receivers[eg]], f2ord(gate));
            }
        }
    }
}

// ---------------------------------------------------------------------------
// aggr (softmax fused): w = exp(gate - segmax); denom += w; aggr += w*msg.
// Normalization happens at node-gather (sum/denom == sum of attn*msg).
// ---------------------------------------------------------------------------
__global__ __launch_bounds__(256)
void aggr_kernel(const int* __restrict__ receivers, int E) {
    int e = (blockIdx.x * blockDim.x + threadIdx.x) >> 5;
    int lane = threadIdx.x & 31;
    if (e >= E) return;
    int r = receivers[e];
    float w = expf(g_gate[e] - ord2f(g_segmax[r]));
    if (lane == 0) atomicAdd(&g_denom[r], w);
    float4 v = *(const float4*)(g_msgs + (size_t)e * 128 + lane * 4);
    float* dst = g_aggr + (size_t)r * 128 + lane * 4;
    atomicAdd(dst + 0, w * v.x);
    atomicAdd(dst + 1, w * v.y);
    atomicAdd(dst + 2, w * v.z);
    atomicAdd(dst + 3, w * v.w);
}

// ---------------------------------------------------------------------------
// node kernel: smem: sA[64*264 h]=33792 | sB 33792 | sW 36864
// ---------------------------------------------------------------------------
__global__ __launch_bounds__(256, 2)
void node_kernel(
    const float* __restrict__ nodes,
    const float* __restrict__ ub1, const float* __restrict__ ub2,
    const float* __restrict__ ub3, float* __restrict__ out, int N)
{
    extern __shared__ unsigned char smem[];
    __half* sA = (__half*)smem;                    // stride 264
    __half* sB = (__half*)(smem + 33792);
    unsigned char* sW = smem + 67584;

    const int tid = threadIdx.x, lane = tid & 31, warp = tid >> 5;
    const int n0 = blockIdx.x * 64;

#pragma unroll
    for (int i = 0; i < 8; i++) {
        int e = warp * 8 + i;
        int n = n0 + e;
        __half* dst = sA + e * 264;
        if (n < N) {
            float4 v0 = *(const float4*)(nodes + (size_t)n * 128 + lane * 4);
            *(__half2*)(dst + lane * 4)     = __floats2half2_rn(v0.x, v0.y);
            *(__half2*)(dst + lane * 4 + 2) = __floats2half2_rn(v0.z, v0.w);
            float d = g_denom[n];
            float inv = d > 0.f ? 1.f / d : 0.f;   // edge-less nodes -> aggr 0
            float4 v1 = *(const float4*)(g_aggr + (size_t)n * 128 + lane * 4);
            *(__half2*)(dst + 128 + lane * 4)     = __floats2half2_rn(inv * v1.x, inv * v1.y);
            *(__half2*)(dst + 128 + lane * 4 + 2) = __floats2half2_rn(inv * v1.z, inv * v1.w);
        } else {
            *(float2*)(dst + lane * 4) = make_float2(0.f, 0.f);
            *(float2*)(dst + 128 + lane * 4) = make_float2(0.f, 0.f);
        }
    }

    mma_layer<256, 256, true , 264, 264>(sA, g_wpack + OFF_UW1, ub1, sB, sW, nullptr, 0, 0);
    mma_layer<256, 256, false, 264, 264>(sB, g_wpack + OFF_UW2, ub2, sA, sW, nullptr, 0, 0);
    mma_layer<256, 128, false, 264, 136>(sA, g_wpack + OFF_UW3, ub3, sB, sW, out, n0, N);
}

// ---------------------------------------------------------------------------
extern "C" void kernel_launch(void* const* d_in, const int* in_sizes, int n_in,
                              void* d_out, int out_size)
{
    const float* nodes     = (const float*)d_in[0];
    const float* edges     = (const float*)d_in[1];
    const int*   senders   = (const int*)  d_in[2];
    const int*   receivers = (const int*)  d_in[3];
    const float* mw1 = (const float*)d_in[4];  const float* mb1 = (const float*)d_in[5];
    const float* mw2 = (const float*)d_in[6];  const float* mb2 = (const float*)d_in[7];
    const float* mw3 = (const float*)d_in[8];  const float* mb3 = (const float*)d_in[9];
    const float* aw1 = (const float*)d_in[10]; const float* ab1 = (const float*)d_in[11];
    const float* aw2 = (const float*)d_in[12]; const float* ab2 = (const float*)d_in[13];
    const float* aw3 = (const float*)d_in[14]; const float* ab3 = (const float*)d_in[15];
    const float* uw1 = (const float*)d_in[16]; const float* ub1 = (const float*)d_in[17];
    const float* uw2 = (const float*)d_in[18]; const float* ub2 = (const float*)d_in[19];
    const float* uw3 = (const float*)d_in[20]; const float* ub3 = (const float*)d_in[21];
    float* out = (float*)d_out;

    const int N = in_sizes[0] / 128;
    const int E = in_sizes[2];

    const int EDGE_SMEM = 106496;
    const int NODE_SMEM = 104448;
    cudaFuncSetAttribute(edge_kernel, cudaFuncAttributeMaxDynamicSharedMemorySize, EDGE_SMEM);
    cudaFuncSetAttribute(node_kernel, cudaFuncAttributeMaxDynamicSharedMemorySize, NODE_SMEM);

    // 0) pack all weights (one kernel)
    pack_kernel<<<(364544 + 255) / 256, 256>>>(mw1, mw2, mw3, aw1, aw2, uw1, uw2, uw3);
    // 1) init scratch
    init_kernel<<<(N * 128 + 255) / 256, 256>>>(N);
    // 2) edge + gate MLP
    edge_kernel<<<(E + 63) / 64, 256, EDGE_SMEM>>>(
        nodes, edges, senders, receivers,
        mb1, mb2, mb3, ab1, ab2, aw3, ab3, E);
    // 3) fused softmax + scatter
    aggr_kernel<<<(E + 7) / 8, 256>>>(receivers, E);
    // 4) node update
    node_kernel<<<(N + 63) / 64, 256, NODE_SMEM>>>(
        nodes, ub1, ub2, ub3, out, N);
}

// round 9
// speedup vs baseline: 3.0086x; 1.1579x over previous
#include <cuda_runtime.h>
#include <cuda_fp16.h>
#include <cstdint>

#define NMAX 50048
#define EMAX 400000

__device__ float g_denom[NMAX];
__device__ float g_aggr[(size_t)NMAX * 128];
// packed fp16 weights: per 16-K slab, [NOUT][24] halves (48B rows)
__device__ __align__(16) unsigned char g_wpack[1093632];

#define OFF_MW1 0u
#define OFF_MW2 208896u
#define OFF_MW3 405504u
#define OFF_AW1 503808u
#define OFF_AW2 552960u
#define OFF_UW1 602112u
#define OFF_UW2 798720u
#define OFF_UW3 995328u

__device__ __forceinline__ uint32_t smem_u32(const void* p) {
    return (uint32_t)__cvta_generic_to_shared(p);
}
__device__ __forceinline__ void ldsm4(uint32_t& r0, uint32_t& r1,
                                      uint32_t& r2, uint32_t& r3, uint32_t a) {
    asm volatile("ldmatrix.sync.aligned.m8n8.x4.shared.b16 {%0,%1,%2,%3}, [%4];"
                 : "=r"(r0), "=r"(r1), "=r"(r2), "=r"(r3) : "r"(a));
}
__device__ __forceinline__ void mma_f16(float c[4],
    uint32_t a0, uint32_t a1, uint32_t a2, uint32_t a3, uint32_t b0, uint32_t b1)
{
    asm volatile(
        "mma.sync.aligned.m16n8k16.row.col.f32.f16.f16.f32 "
        "{%0,%1,%2,%3}, {%4,%5,%6,%7}, {%8,%9}, {%0,%1,%2,%3};"
        : "+f"(c[0]), "+f"(c[1]), "+f"(c[2]), "+f"(c[3])
        : "r"(a0), "r"(a1), "r"(a2), "r"(a3), "r"(b0), "r"(b1));
}

#define WSTAGE 1536
#define WREGION 4608

// ---------------------------------------------------------------------------
// Warp-autonomous fp16 MLP layer over 64 rows (see R8 comments).
// ---------------------------------------------------------------------------
template<int K, int NOUT, bool RELU, int LDIN, int LDOUT>
__device__ __forceinline__ void mma_layer(
    const __half* __restrict__ sIn, const unsigned char* __restrict__ Wp,
    const float* __restrict__ Bv, __half* __restrict__ sOut,
    unsigned char* __restrict__ sWbase,
    float* __restrict__ gOut, int row0, int rowlim)
{
    constexpr int NSLAB = K / 16;
    constexpr int NW = NOUT / 8;
    constexpr int NT = NW / 8;
    constexpr int WCH = NW * 48 / 16;
    const int tid = threadIdx.x, lane = tid & 31, warp = tid >> 5;
    const int n0 = warp * NW;
    unsigned char* wb = sWbase + warp * WREGION;
    const int g = lane >> 2, tg = lane & 3;
    const int a_row = (lane & 7) + ((lane >> 3) & 1) * 8;
    const int a_k   = (lane >> 4) * 8;
    const int b_n   = ((lane >> 4) & 1) * 8 + (lane & 7);
    const int b_k   = ((lane >> 3) & 1) * 8;

    auto issue = [&](int s) {
        if (s < NSLAB) {
            const unsigned char* src = Wp + ((size_t)s * NOUT + n0) * 48;
            unsigned char* dst = wb + (s % 3) * WSTAGE;
#pragma unroll
            for (int c = lane; c < WCH; c += 32) {
                uint32_t da = smem_u32(dst + c * 16);
                asm volatile("cp.async.ca.shared.global [%0], [%1], 16;"
                             :: "r"(da), "l"(src + c * 16));
            }
        }
        asm volatile("cp.async.commit_group;");
    };

    issue(0); issue(1); issue(2);
    __syncthreads();   // sIn ready

    float acc[4][NT][4];
#pragma unroll
    for (int mt = 0; mt < 4; mt++)
#pragma unroll
        for (int nt = 0; nt < NT; nt++)
#pragma unroll
            for (int q = 0; q < 4; q++) acc[mt][nt][q] = 0.f;

    for (int s = 0; s < NSLAB; s++) {
        asm volatile("cp.async.wait_group 2;" ::: "memory");
        __syncwarp();
        const unsigned char* buf = wb + (s % 3) * WSTAGE;
        const int kc = s * 16;
        uint32_t A[4][4];
#pragma unroll
        for (int mt = 0; mt < 4; mt++)
            ldsm4(A[mt][0], A[mt][1], A[mt][2], A[mt][3],
                  smem_u32(sIn + (mt * 16 + a_row) * LDIN + kc + a_k));
#pragma unroll
        for (int ng = 0; ng < NT / 2; ng++) {
            uint32_t B0, B1, B2, B3;
            ldsm4(B0, B1, B2, B3, smem_u32(buf + (ng * 16 + b_n) * 48 + b_k * 2));
#pragma unroll
            for (int mt = 0; mt < 4; mt++) {
                mma_f16(acc[mt][2 * ng],     A[mt][0], A[mt][1], A[mt][2], A[mt][3], B0, B1);
                mma_f16(acc[mt][2 * ng + 1], A[mt][0], A[mt][1], A[mt][2], A[mt][3], B2, B3);
            }
        }
        issue(s + 3);
    }

#pragma unroll
    for (int nt = 0; nt < NT; nt++) {
        int c = n0 + nt * 8 + 2 * tg;
        float b0 = __ldg(Bv + c), b1 = __ldg(Bv + c + 1);
#pragma unroll
        for (int mt = 0; mt < 4; mt++) {
#pragma unroll
            for (int h = 0; h < 2; h++) {
                int r = mt * 16 + g + h * 8;
                float v0 = acc[mt][nt][h * 2 + 0] + b0;
                float v1 = acc[mt][nt][h * 2 + 1] + b1;
                if (RELU) { v0 = fmaxf(v0, 0.f); v1 = fmaxf(v1, 0.f); }
                *(__half2*)(sOut + r * LDOUT + c) = __floats2half2_rn(v0, v1);
                if (gOut != nullptr && row0 + r < rowlim)
                    *(float2*)(gOut + (size_t)(row0 + r) * NOUT + c) =
                        make_float2(v0, v1);
            }
        }
    }
    __syncthreads();
}

// ---------------------------------------------------------------------------
// G2 variant: no smem output; folds the gate dot (output . aw3) into the
// epilogue. Each warp covers 16 cols; partials quad-reduced (shfl over tg)
// and written to sdot[row*8 + warp].
// ---------------------------------------------------------------------------
template<int K, int LDIN>
__device__ __forceinline__ void mma_layer_dot(
    const __half* __restrict__ sIn, const unsigned char* __restrict__ Wp,
    const float* __restrict__ Bv, const float* __restrict__ aw3,
    float* __restrict__ sdot, unsigned char* __restrict__ sWbase)
{
    constexpr int NOUT = 128, NSLAB = K / 16, NW = 16, NT = 2, WCH = NW * 48 / 16;
    const int tid = threadIdx.x, lane = tid & 31, warp = tid >> 5;
    const int n0 = warp * NW;
    unsigned char* wb = sWbase + warp * WREGION;
    const int g = lane >> 2, tg = lane & 3;
    const int a_row = (lane & 7) + ((lane >> 3) & 1) * 8;
    const int a_k   = (lane >> 4) * 8;
    const int b_n   = ((lane >> 4) & 1) * 8 + (lane & 7);
    const int b_k   = ((lane >> 3) & 1) * 8;

    auto issue = [&](int s) {
        if (s < NSLAB) {
            const unsigned char* src = Wp + ((size_t)s * NOUT + n0) * 48;
            unsigned char* dst = wb + (s % 3) * WSTAGE;
#pragma unroll
            for (int c = lane; c < WCH; c += 32) {
                uint32_t da = smem_u32(dst + c * 16);
                asm volatile("cp.async.ca.shared.global [%0], [%1], 16;"
                             :: "r"(da), "l"(src + c * 16));
            }
        }
        asm volatile("cp.async.commit_group;");
    };

    issue(0); issue(1); issue(2);
    __syncthreads();

    float acc[4][NT][4];
#pragma unroll
    for (int mt = 0; mt < 4; mt++)
#pragma unroll
        for (int nt = 0; nt < NT; nt++)
#pragma unroll
            for (int q = 0; q < 4; q++) acc[mt][nt][q] = 0.f;

    for (int s = 0; s < NSLAB; s++) {
        asm volatile("cp.async.wait_group 2;" ::: "memory");
        __syncwarp();
        const unsigned char* buf = wb + (s % 3) * WSTAGE;
        const int kc = s * 16;
        uint32_t A[4][4];
#pragma unroll
        for (int mt = 0; mt < 4; mt++)
            ldsm4(A[mt][0], A[mt][1], A[mt][2], A[mt][3],
                  smem_u32(sIn + (mt * 16 + a_row) * LDIN + kc + a_k));
        uint32_t B0, B1, B2, B3;
        ldsm4(B0, B1, B2, B3, smem_u32(buf + b_n * 48 + b_k * 2));
#pragma unroll
        for (int mt = 0; mt < 4; mt++) {
            mma_f16(acc[mt][0], A[mt][0], A[mt][1], A[mt][2], A[mt][3], B0, B1);
            mma_f16(acc[mt][1], A[mt][0], A[mt][1], A[mt][2], A[mt][3], B2, B3);
        }
        issue(s + 3);
    }

    // epilogue: dot with aw3 over this warp's 16 cols, per row
    float dp[4][2];
#pragma unroll
    for (int mt = 0; mt < 4; mt++) { dp[mt][0] = 0.f; dp[mt][1] = 0.f; }
#pragma unroll
    for (int nt = 0; nt < NT; nt++) {
        int c = n0 + nt * 8 + 2 * tg;
        float b0 = __ldg(Bv + c), b1 = __ldg(Bv + c + 1);
        float a0 = __ldg(aw3 + c), a1 = __ldg(aw3 + c + 1);
#pragma unroll
        for (int mt = 0; mt < 4; mt++) {
#pragma unroll
            for (int h = 0; h < 2; h++) {
                float v0 = acc[mt][nt][h * 2 + 0] + b0;
                float v1 = acc[mt][nt][h * 2 + 1] + b1;
                dp[mt][h] += v0 * a0 + v1 * a1;
            }
        }
    }
#pragma unroll
    for (int mt = 0; mt < 4; mt++)
#pragma unroll
        for (int h = 0; h < 2; h++) {
            dp[mt][h] += __shfl_xor_sync(0xffffffffu, dp[mt][h], 1);
            dp[mt][h] += __shfl_xor_sync(0xffffffffu, dp[mt][h], 2);
            if (tg == 0) {
                int r = mt * 16 + g + h * 8;
                sdot[r * 8 + warp] = dp[mt][h];
            }
        }
    __syncthreads();
}

// ---------------------------------------------------------------------------
__device__ __forceinline__ void pack_one(const float* src, int idx, int N,
                                         unsigned int off) {
    int k = idx / N, n = idx - k * N;
    *(__half*)(g_wpack + off + (((size_t)(k >> 4) * N + n) * 24 + (k & 15)) * 2) =
        __float2half_rn(src[idx]);
}
__global__ void pack_kernel(
    const float* __restrict__ mw1, const float* __restrict__ mw2,
    const float* __restrict__ mw3, const float* __restrict__ aw1,
    const float* __restrict__ aw2, const float* __restrict__ uw1,
    const float* __restrict__ uw2, const float* __restrict__ uw3)
{
    int idx = blockIdx.x * blockDim.x + threadIdx.x;
    if      (idx <  69632) pack_one(mw1, idx,          256, OFF_MW1);
    else if (idx < 135168) pack_one(mw2, idx -  69632, 256, OFF_MW2);
    else if (idx < 167936) pack_one(mw3, idx - 135168, 128, OFF_MW3);
    else if (idx < 184320) pack_one(aw1, idx - 167936, 128, OFF_AW1);
    else if (idx < 200704) pack_one(aw2, idx - 184320, 128, OFF_AW2);
    else if (idx < 266240) pack_one(uw1, idx - 200704, 256, OFF_UW1);
    else if (idx < 331776) pack_one(uw2, idx - 266240, 256, OFF_UW2);
    else if (idx < 364544) pack_one(uw3, idx - 331776, 128, OFF_UW3);
}

__global__ void init_kernel(int N) {
    int idx = blockIdx.x * blockDim.x + threadIdx.x;
    if (idx < N * 128) g_aggr[idx] = 0.f;
    if (idx < N) g_denom[idx] = 0.f;
}

// ---------------------------------------------------------------------------
// edge kernel: full fusion — MLPs + gate + softmax-weight + scatter.
// smem: sA 35840 | sB 33792 | sW 36864 | sdot 2048 | swexp 256  = 108800 B
// ---------------------------------------------------------------------------
__global__ __launch_bounds__(256, 2)
void edge_kernel(
    const float* __restrict__ nodes, const float* __restrict__ edges,
    const int* __restrict__ senders, const int* __restrict__ receivers,
    const float* __restrict__ b1, const float* __restrict__ b2,
    const float* __restrict__ b3, const float* __restrict__ ab1,
    const float* __restrict__ ab2,
    const float* __restrict__ aw3, const float* __restrict__ ab3, int E)
{
    extern __shared__ unsigned char smem[];
    __half* sA = (__half*)smem;                    // stride 280 (or 136)
    __half* sB = (__half*)(smem + 35840);          // stride 264 (or 136)
    unsigned char* sW = smem + 69632;
    float* sdot = (float*)(smem + 106496);         // [64][8]
    float* swexp = (float*)(smem + 108544);        // [64]

    const int tid = threadIdx.x, lane = tid & 31, warp = tid >> 5;
    const int e0 = blockIdx.x * 64;

#pragma unroll
    for (int i = 0; i < 8; i++) {
        int e = warp * 8 + i;
        int eg = e0 + e;
        int egc = eg < E ? eg : E - 1;
        int s = senders[egc], r = receivers[egc];
        __half* dst = sA + e * 280;
        if (lane < 4) {
            float4 v = *(const float4*)(edges + (size_t)egc * 16 + lane * 4);
            *(__half2*)(dst + lane * 4)     = __floats2half2_rn(v.x, v.y);
            *(__half2*)(dst + lane * 4 + 2) = __floats2half2_rn(v.z, v.w);
        }
        float4 vs = *(const float4*)(nodes + (size_t)s * 128 + lane * 4);
        *(__half2*)(dst + 16 + lane * 4)     = __floats2half2_rn(vs.x, vs.y);
        *(__half2*)(dst + 16 + lane * 4 + 2) = __floats2half2_rn(vs.z, vs.w);
        float4 vr = *(const float4*)(nodes + (size_t)r * 128 + lane * 4);
        *(__half2*)(dst + 144 + lane * 4)     = __floats2half2_rn(vr.x, vr.y);
        *(__half2*)(dst + 144 + lane * 4 + 2) = __floats2half2_rn(vr.z, vr.w);
    }

    mma_layer<272, 256, true , 280, 264>(sA, g_wpack + OFF_MW1, b1, sB, sW, nullptr, 0, 0);
    mma_layer<256, 256, false, 264, 280>(sB, g_wpack + OFF_MW2, b2, sA, sW, nullptr, 0, 0);
    mma_layer<256, 128, false, 280, 136>(sA, g_wpack + OFF_MW3, b3, sB, sW, nullptr, 0, 0);
    mma_layer<128, 128, true , 136, 136>(sB, g_wpack + OFF_AW1, ab1, sA, sW, nullptr, 0, 0);
    mma_layer_dot<128, 136>(sA, g_wpack + OFF_AW2, ab2, aw3, sdot, sW);

    // finalize gates: w = exp(gate) (max-free softmax; exact in real arith)
    if (tid < 64) {
        int eg = e0 + tid;
        float w = 0.f;
        if (eg < E) {
            float gate = __ldg(ab3);
#pragma unroll
            for (int j = 0; j < 8; j++) gate += sdot[tid * 8 + j];
            w = expf(gate);
            atomicAdd(&g_denom[receivers[eg]], w);
        }
        swexp[tid] = w;
    }
    __syncthreads();

    // scatter: aggr[recv] += w * msg (msgs are fp16 in sB, stride 136)
#pragma unroll
    for (int i = 0; i < 8; i++) {
        int e = warp * 8 + i;
        int eg = e0 + e;
        if (eg >= E) continue;
        float w = swexp[e];
        int r = receivers[eg];
        __half2 p0 = *(__half2*)(sB + e * 136 + lane * 4);
        __half2 p1 = *(__half2*)(sB + e * 136 + lane * 4 + 2);
        float2 f0 = __half22float2(p0), f1 = __half22float2(p1);
        float* dst = g_aggr + (size_t)r * 128 + lane * 4;
        atomicAdd(dst + 0, w * f0.x);
        atomicAdd(dst + 1, w * f0.y);
        atomicAdd(dst + 2, w * f1.x);
        atomicAdd(dst + 3, w * f1.y);
    }
}

// ---------------------------------------------------------------------------
// node kernel (unchanged from R8): normalizes aggr by denom at gather.
// ---------------------------------------------------------------------------
__global__ __launch_bounds__(256, 2)
void node_kernel(
    const float* __restrict__ nodes,
    const float* __restrict__ ub1, const float* __restrict__ ub2,
    const float* __restrict__ ub3, float* __restrict__ out, int N)
{
    extern __shared__ unsigned char smem[];
    __half* sA = (__half*)smem;                    // stride 264
    __half* sB = (__half*)(smem + 33792);
    unsigned char* sW = smem + 67584;

    const int tid = threadIdx.x, lane = tid & 31, warp = tid >> 5;
    const int n0 = blockIdx.x * 64;

#pragma unroll
    for (int i = 0; i < 8; i++) {
        int e = warp * 8 + i;
        int n = n0 + e;
        __half* dst = sA + e * 264;
        if (n < N) {
            float4 v0 = *(const float4*)(nodes + (size_t)n * 128 + lane * 4);
            *(__half2*)(dst + lane * 4)     = __floats2half2_rn(v0.x, v0.y);
            *(__half2*)(dst + lane * 4 + 2) = __floats2half2_rn(v0.z, v0.w);
            float d = g_denom[n];
            float inv = d > 0.f ? 1.f / d : 0.f;
            float4 v1 = *(const float4*)(g_aggr + (size_t)n * 128 + lane * 4);
            *(__half2*)(dst + 128 + lane * 4)     = __floats2half2_rn(inv * v1.x, inv * v1.y);
            *(__half2*)(dst + 128 + lane * 4 + 2) = __floats2half2_rn(inv * v1.z, inv * v1.w);
        } else {
            *(float2*)(dst + lane * 4) = make_float2(0.f, 0.f);
            *(float2*)(dst + 128 + lane * 4) = make_float2(0.f, 0.f);
        }
    }

    mma_layer<256, 256, true , 264, 264>(sA, g_wpack + OFF_UW1, ub1, sB, sW, nullptr, 0, 0);
    mma_layer<256, 256, false, 264, 264>(sB, g_wpack + OFF_UW2, ub2, sA, sW, nullptr, 0, 0);
    mma_layer<256, 128, false, 264, 136>(sA, g_wpack + OFF_UW3, ub3, sB, sW, out, n0, N);
}

// ---------------------------------------------------------------------------
extern "C" void kernel_launch(void* const* d_in, const int* in_sizes, int n_in,
                              void* d_out, int out_size)
{
    const float* nodes     = (const float*)d_in[0];
    const float* edges     = (const float*)d_in[1];
    const int*   senders   = (const int*)  d_in[2];
    const int*   receivers = (const int*)  d_in[3];
    const float* mw1 = (const float*)d_in[4];  const float* mb1 = (const float*)d_in[5];
    const float* mw2 = (const float*)d_in[6];  const float* mb2 = (const float*)d_in[7];
    const float* mw3 = (const float*)d_in[8];  const float* mb3 = (const float*)d_in[9];
    const float* aw1 = (const float*)d_in[10]; const float* ab1 = (const float*)d_in[11];
    const float* aw2 = (const float*)d_in[12]; const float* ab2 = (const float*)d_in[13];
    const float* aw3 = (const float*)d_in[14]; const float* ab3 = (const float*)d_in[15];
    const float* uw1 = (const float*)d_in[16]; const float* ub1 = (const float*)d_in[17];
    const float* uw2 = (const float*)d_in[18]; const float* ub2 = (const float*)d_in[19];
    const float* uw3 = (const float*)d_in[20]; const float* ub3 = (const float*)d_in[21];
    float* out = (float*)d_out;

    const int N = in_sizes[0] / 128;
    const int E = in_sizes[2];

    const int EDGE_SMEM = 108800;
    const int NODE_SMEM = 104448;
    cudaFuncSetAttribute(edge_kernel, cudaFuncAttributeMaxDynamicSharedMemorySize, EDGE_SMEM);
    cudaFuncSetAttribute(node_kernel, cudaFuncAttributeMaxDynamicSharedMemorySize, NODE_SMEM);

    pack_kernel<<<(364544 + 255) / 256, 256>>>(mw1, mw2, mw3, aw1, aw2, uw1, uw2, uw3);
    init_kernel<<<(N * 128 + 255) / 256, 256>>>(N);

    edge_kernel<<<(E + 63) / 64, 256, EDGE_SMEM>>>(
        nodes, edges, senders, receivers,
        mb1, mb2, mb3, ab1, ab2, aw3, ab3, E);

    node_kernel<<<(N + 63) / 64, 256, NODE_SMEM>>>(
        nodes, ub1, ub2, ub3, out, N);
}